// round 15
// baseline (speedup 1.0000x reference)
#include <cuda_runtime.h>

#define BB 32
#define PP 32768
#define OO 32
#define CBLK 256
#define NBLK (PP / CBLK)   // 128
#define NBIN 2048
#define NCOPY 16
#define SEL_SMEM (NCOPY * NBIN * 4)

// ---------------- scratch (zero-initialized at module load; self-resetting) ----
__device__ unsigned long long g_bp_key[BB * OO];   // 0 is a valid identity for atomicMax
__device__ float g_ce[BB * PP];
__device__ int   g_hist[BB * NBIN];                // zeroed by k_select after use
__device__ float g_pl[BB * NBLK], g_pc[BB * NBLK];
__device__ int   g_pn[BB * NBLK];
__device__ float g_cl[BB], g_cc[BB];
__device__ int   g_cn[BB];
__device__ float g_bl[BB], g_bc[BB], g_bt[BB];
__device__ int   g_bn[BB];
__device__ int   g_bdone[BB];                      // per-batch block-completion counter
__device__ int   g_done;                           // reset by finalizer

// ---------------- shared math helpers ----------------
__device__ __forceinline__ float iou_f(float tx1, float ty1, float tx2, float ty2, float tar,
                                       float px1, float py1, float px2, float py2, float pa) {
    float ww = fmaxf(fminf(tx2, px2) - fmaxf(tx1, px1), 0.0f);
    float hh = fmaxf(fminf(ty2, py2) - fmaxf(ty1, py1), 0.0f);
    float inter = ww * hh;
    return __fdividef(inter, (tar + pa) - inter);
}

__device__ __forceinline__ void loss_terms(float ov, float lbl,
                                           float mtx1, float mty1, float mtx2, float mty2,
                                           float prx, float pry, float prz, float prw,
                                           float q0, float q1, float q2,
                                           float cx, float cy,
                                           bool& pos, float& lloss, float& ce, float& cem) {
    int cls = (ov < 0.5f) ? 0 : (int)lbl;
    pos = cls > 0;
    float gx = __fdividef((mtx1 + mtx2) * 0.5f - prx, 0.1f * prz);
    float gy = __fdividef((mty1 + mty2) * 0.5f - pry, 0.1f * prw);
    float gw = __logf(__fdividef(mtx2 - mtx1, prz)) * 5.0f;
    float gh = __logf(__fdividef(mty2 - mty1, prw)) * 5.0f;
    float d0 = q0 - gx, d1 = q1 - gy, d2 = q2 - gw, d3 = q2 - gh;
    float a0 = fabsf(d0), a1 = fabsf(d1), a2 = fabsf(d2), a3 = fabsf(d3);
    float t0 = (a0 < 1.0f) ? 0.5f * d0 * d0 : a0 - 0.5f;
    float t1 = (a1 < 1.0f) ? 0.5f * d1 * d1 : a1 - 0.5f;
    float t2 = (a2 < 1.0f) ? 0.5f * d2 * d2 : a2 - 0.5f;
    float t3 = (a3 < 1.0f) ? 0.5f * d3 * d3 : a3 - 0.5f;
    lloss = (t0 + t1) + (t2 + t3);
    float m = fmaxf(cx, cy);
    float lse = m + __logf(__expf(cx - m) + __expf(cy - m));
    float picked = cls ? cy : cx;
    ce = lse - picked;
    cem = pos ? 0.0f : fmaxf(ce, 0.0f);
}

// ---------------- override correction (warp 0 of the last block per batch) ----
// __noinline__ firewall: keeps the tail's register demand out of the hot loop.
__device__ __noinline__ void do_correction(int b, int lane,
                                           const float*  __restrict__ loc,
                                           const float2* __restrict__ conf,
                                           const float4* __restrict__ priors,
                                           const float4* s_tb, const float* s_ta,
                                           const float* s_tl) {
    __threadfence();                         // acquire: other blocks' g_ce/g_bp_key/g_hist
    const int o = lane;
    unsigned p = 0xFFFFFFFFu - (unsigned)(g_bp_key[b * OO + o] & 0xFFFFFFFFull);
    g_bp_key[b * OO + o] = 0ull;             // reset for next replay (0 = valid identity)
    unsigned mm = __match_any_sync(0xffffffffu, p);
    bool active = (31 - __clz(mm)) == o;     // last-o-wins dedup

    float4 pr = priors[p];
    float px1 = pr.x - pr.z * 0.5f, py1 = pr.y - pr.w * 0.5f;
    float px2 = pr.x + pr.z * 0.5f, py2 = pr.y + pr.w * 0.5f;
    float pa = (px2 - px1) * (py2 - py1);

    // recompute old best_truth with the SAME math/order as the main loop
    unsigned obu = 0u; int obi = 0;
    #pragma unroll
    for (int o2 = 0; o2 < OO; o2++) {
        float4 tb = s_tb[o2];
        float iou = iou_f(tb.x, tb.y, tb.z, tb.w, s_ta[o2],
                          px1, py1, px2, py2, pa);
        unsigned u = __float_as_uint(iou);
        if (u > obu) { obu = u; obi = o2; }
    }
    float obv = __uint_as_float(obu);

    const size_t bp = (size_t)b * PP + p;
    const float* l = loc + bp * 3;
    float q0 = l[0], q1 = l[1], q2 = l[2];
    float2 c = conf[bp];

    float4 tbo = s_tb[obi];
    bool pos_o; float ll_o, ce_o, cem_o;
    loss_terms(obv, s_tl[obi], tbo.x, tbo.y, tbo.z, tbo.w,
               pr.x, pr.y, pr.z, pr.w, q0, q1, q2, c.x, c.y,
               pos_o, ll_o, ce_o, cem_o);
    float4 tbn = s_tb[o];
    bool pos_n; float ll_n, ce_n, cem_n;
    loss_terms(2.0f, s_tl[o], tbn.x, tbn.y, tbn.z, tbn.w,
               pr.x, pr.y, pr.z, pr.w, q0, q1, q2, c.x, c.y,
               pos_n, ll_n, ce_n, cem_n);

    float dl = 0.f, dc = 0.f; int dn = 0;
    if (active) {
        float stored = g_ce[bp];             // exact bits the owning block wrote
        g_ce[bp] = cem_n;
        int ob = (int)(__float_as_uint(stored) >> 21);
        int nb = (int)(__float_as_uint(cem_n) >> 21);
        if (ob != nb) {
            atomicAdd(&g_hist[b * NBIN + ob], -1);
            atomicAdd(&g_hist[b * NBIN + nb], 1);
        }
        dl = (pos_n ? ll_n : 0.f) - (pos_o ? ll_o : 0.f);
        dc = (pos_n ? ce_n : 0.f) - (pos_o ? ce_o : 0.f);
        dn = (pos_n ? 1 : 0) - (pos_o ? 1 : 0);
    }
    #pragma unroll
    for (int s = 16; s; s >>= 1) {
        dl += __shfl_down_sync(0xffffffffu, dl, s);
        dc += __shfl_down_sync(0xffffffffu, dc, s);
        dn += __shfl_down_sync(0xffffffffu, dn, s);
    }
    if (o == 0) { g_cl[b] = dl; g_cc[b] = dc; g_cn[b] = dn; g_bdone[b] = 0; }
}

// ---------------- fused match + loss + histogram + tail correction -----------
__global__ __launch_bounds__(CBLK, 6) void k_main(const float*  __restrict__ loc,
                                                  const float2* __restrict__ conf,
                                                  const float4* __restrict__ priors,
                                                  const float*  __restrict__ targets) {
    __shared__ float4 s_tb[OO];                  // truth box (x1,y1,x2,y2)
    __shared__ float  s_ta[OO];                  // truth area
    __shared__ float  s_tl[OO];                  // truth label
    __shared__ unsigned long long sbest[OO];
    __shared__ unsigned s_m[8][OO * 33];         // per-warp 32x32 iou tile, padded
    __shared__ float swl[8], swc[8];
    __shared__ int   swn[8];
    __shared__ int   s_prev;
    const int b = blockIdx.y, tid = threadIdx.x;
    const int lane = tid & 31, w = tid >> 5;

    if (tid < OO) {
        const float* t = targets + (size_t)(b * OO + tid) * 5;
        float x1 = t[0], y1 = t[1], x2 = t[2], y2 = t[3];
        s_tb[tid] = make_float4(x1, y1, x2, y2);
        s_ta[tid] = (x2 - x1) * (y2 - y1);
        s_tl[tid] = t[4];
        sbest[tid] = 0ull;
    }
    const int pblk = blockIdx.x * CBLK;
    const int p = pblk + tid;
    float4 pr = priors[p];
    const float Px1 = pr.x - pr.z * 0.5f, Py1 = pr.y - pr.w * 0.5f;
    const float Px2 = pr.x + pr.z * 0.5f, Py2 = pr.y + pr.w * 0.5f;
    const float Pa  = (Px2 - Px1) * (Py2 - Py1);
    __syncthreads();

    unsigned* mrow = s_m[w];
    unsigned best_u = 0u; int best_o = 0;        // per-prior best truth (local)

    #pragma unroll
    for (int o = 0; o < 32; o++) {
        float4 tb = s_tb[o];                     // LDS.128 broadcast
        float  ta = s_ta[o];                     // LDS.32 broadcast
        float ww = fmaxf(fminf(tb.z, Px2) - fmaxf(tb.x, Px1), 0.0f);
        float hh = fmaxf(fminf(tb.w, Py2) - fmaxf(tb.y, Py1), 0.0f);
        float inter = ww * hh;
        float iou = __fdividef(inter, (ta + Pa) - inter);
        unsigned u = __float_as_uint(iou);
        mrow[lane * 33 + o] = u;                 // conflict-free STS
        if (u > best_u) { best_u = u; best_o = o; }   // first-index on ties
    }
    __syncwarp();

    // per-truth argmax over this warp's 32 priors (lane = truth)
    {
        unsigned tu = 0u; int tk = 0;
        #pragma unroll
        for (int k = 0; k < 32; k++) {
            unsigned u = mrow[k * 33 + lane];
            if (u > tu) { tu = u; tk = k; }      // ascending prior index, strict > = first
        }
        unsigned long long key = ((unsigned long long)tu << 32) |
                                 (unsigned)(0xFFFFFFFFu - (unsigned)(pblk + w * 32 + tk));
        atomicMax(&sbest[lane], key);
    }

    // ---- loss for my prior ----
    const size_t bp = (size_t)b * PP + p;
    const int idx = best_o;
    const float my_bto = __uint_as_float(best_u);
    float4 tb2 = s_tb[idx];
    const float* l = loc + bp * 3;
    float q0 = l[0], q1 = l[1], q2 = l[2];
    float2 c = conf[bp];

    bool pos; float lloss, ce, cem;
    loss_terms(my_bto, s_tl[idx],
               tb2.x, tb2.y, tb2.z, tb2.w,
               pr.x, pr.y, pr.z, pr.w, q0, q1, q2, c.x, c.y,
               pos, lloss, ce, cem);
    g_ce[bp] = cem;

    {   // distributed warp-aggregated histogram of ce_mine top-11 bits
        unsigned bin = __float_as_uint(cem) >> 21;
        unsigned mm = __match_any_sync(0xffffffffu, bin);
        if ((mm & ((1u << lane) - 1u)) == 0u)
            atomicAdd(&g_hist[b * NBIN + bin], (int)__popc(mm));
    }

    float rl = pos ? lloss : 0.0f;
    float rc = pos ? ce : 0.0f;
    int   rn = pos ? 1 : 0;
    #pragma unroll
    for (int o = 16; o; o >>= 1) {
        rl += __shfl_down_sync(0xffffffffu, rl, o);
        rc += __shfl_down_sync(0xffffffffu, rc, o);
        rn += __shfl_down_sync(0xffffffffu, rn, o);
    }
    if (lane == 0) { swl[w] = rl; swc[w] = rc; swn[w] = rn; }
    __syncthreads();
    if (tid == 0) {
        float sl = 0.f, sc = 0.f; int sn = 0;
        #pragma unroll
        for (int i = 0; i < 8; i++) { sl += swl[i]; sc += swc[i]; sn += swn[i]; }
        int pb = b * NBLK + blockIdx.x;
        g_pl[pb] = sl; g_pc[pb] = sc; g_pn[pb] = sn;
    }
    if (tid < OO) atomicMax(&g_bp_key[b * OO + tid], sbest[tid]);

    // ---- tail: last block of this batch runs the override correction ----
    __syncthreads();                             // all block writes issued
    if (tid == 0) {
        __threadfence();                         // release this block's writes
        s_prev = atomicAdd(&g_bdone[b], 1);
    }
    __syncthreads();
    if (s_prev == NBLK - 1 && w == 0)
        do_correction(b, lane, loc, conf, priors, s_tb, s_ta, s_tl);
}

// ---------------- hierarchical threshold finder (2 barriers) ----------------
__device__ __forceinline__ int find_threshold(int* h, int n, int tid,
                                              int* s_kr, int* s_res, int* s_seg) {
    const int lane = tid & 31, w = tid >> 5;
    const int nseg = n >> 6;   // 64 bins per segment, one warp each
    if (w < nseg) {
        int a = h[(w << 6) + lane] + h[(w << 6) + 32 + lane];
        #pragma unroll
        for (int o = 16; o; o >>= 1) a += __shfl_down_sync(0xffffffffu, a, o);
        if (lane == 0) s_seg[w] = a;
    }
    __syncthreads();
    if (w == 0) {
        int kr = *s_kr;
        int vv = (lane < nseg) ? s_seg[lane] : 0;
        #pragma unroll
        for (int o = 1; o < 32; o <<= 1) {
            int u = __shfl_down_sync(0xffffffffu, vv, o);
            if (lane + o < 32) vv += u;
        }
        unsigned bal = __ballot_sync(0xffffffffu, vv >= kr);
        int seg = 31 - __clz(bal);
        int above = __shfl_sync(0xffffffffu, vv, (seg + 1) & 31);
        if (seg == 31) above = 0;
        int kr2 = kr - above;
        int base = seg << 6;
        int sh = h[base + 32 + lane];
        #pragma unroll
        for (int o = 1; o < 32; o <<= 1) {
            int u = __shfl_down_sync(0xffffffffu, sh, o);
            if (lane + o < 32) sh += u;
        }
        int hi_total = __shfl_sync(0xffffffffu, sh, 0);
        int sl = h[base + lane];
        #pragma unroll
        for (int o = 1; o < 32; o <<= 1) {
            int u = __shfl_down_sync(0xffffffffu, sl, o);
            if (lane + o < 32) sl += u;
        }
        sl += hi_total;
        unsigned balh = __ballot_sync(0xffffffffu, sh >= kr2);
        int sel, kr3;
        if (balh) {
            int l2 = 31 - __clz(balh);
            sel = base + 32 + l2;
            int ab = __shfl_sync(0xffffffffu, sh, (l2 + 1) & 31);
            if (l2 == 31) ab = 0;
            kr3 = kr2 - ab;
        } else {
            unsigned ball = __ballot_sync(0xffffffffu, sl >= kr2);
            int l2 = 31 - __clz(ball);
            sel = base + l2;
            int ab = (l2 == 31) ? hi_total : __shfl_sync(0xffffffffu, sl, (l2 + 1) & 31);
            kr3 = kr2 - ab;
        }
        if (lane == 0) { *s_res = sel; *s_kr = kr3; }
    }
    __syncthreads();
    return *s_res;
}

// ---------------- per-batch top-k + finalize (privatized histograms) ----------
__global__ __launch_bounds__(1024) void k_select(float* __restrict__ out) {
    extern __shared__ int h[];                  // [NCOPY][NBIN]; copy 0 = merged view
    __shared__ int s_seg[32];
    __shared__ float sw32[32];
    __shared__ int s_kr, s_k, s_res;
    __shared__ float s_topk;
    const int b = blockIdx.x, tid = threadIdx.x;
    const int lane = tid & 31, w = tid >> 5;
    const int hbase = (w & (NCOPY - 1)) << 11;  // this warp's private copy

    // load ce values first — warp-contiguous LDG.128 (order-free mapping)
    unsigned v[32];
    {
        const uint4* ce4 = (const uint4*)(g_ce + (size_t)b * PP);
        #pragma unroll
        for (int i = 0; i < 8; i++) {
            uint4 f = ce4[tid + i * 1024];
            v[i * 4 + 0] = f.x;
            v[i * 4 + 1] = f.y;
            v[i * 4 + 2] = f.z;
            v[i * 4 + 3] = f.w;
        }
    }

    // pass-1 histogram comes precomputed into copy 0; zero g_hist for next replay
    h[tid]        = g_hist[b * NBIN + tid];
    h[tid + 1024] = g_hist[b * NBIN + tid + 1024];
    g_hist[b * NBIN + tid] = 0;
    g_hist[b * NBIN + tid + 1024] = 0;

    if (w == 0) {
        float a = 0.f, c = 0.f; int nn = 0;
        #pragma unroll
        for (int j = 0; j < 4; j++) {
            int pb = b * NBLK + lane + 32 * j;
            a += g_pl[pb]; c += g_pc[pb]; nn += g_pn[pb];
        }
        #pragma unroll
        for (int o = 16; o; o >>= 1) {
            a  += __shfl_down_sync(0xffffffffu, a, o);
            c  += __shfl_down_sync(0xffffffffu, c, o);
            nn += __shfl_down_sync(0xffffffffu, nn, o);
        }
        if (lane == 0) {
            a += g_cl[b]; c += g_cc[b]; nn += g_cn[b];
            g_bl[b] = a; g_bc[b] = c; g_bn[b] = nn;
            int k = 3 * nn; if (k > PP - 1) k = PP - 1;
            s_k = k; s_kr = k;
        }
    }
    __syncthreads();

    if (s_k > 0) {
        // pass 1: bits [31:21] (precomputed, copy 0)
        int sel = find_threshold(h, 2048, tid, &s_kr, &s_res, s_seg);
        unsigned pref = (unsigned)sel << 21, prefmask = 0xFFE00000u;

        // pass 2: bits [20:10] — 16-way privatized histograms
        #pragma unroll
        for (int j = 0; j < NCOPY * NBIN / 1024; j++) h[tid + j * 1024] = 0;
        __syncthreads();
        #pragma unroll
        for (int i = 0; i < 32; i++) {
            bool hit = (v[i] & prefmask) == pref;
            unsigned act = __ballot_sync(0xffffffffu, hit);
            if (hit) {
                int bin = (int)((v[i] >> 10) & 0x7FFu);
                unsigned mm = __match_any_sync(act, bin);
                if ((mm & ((1u << lane) - 1u)) == 0u)
                    atomicAdd(&h[hbase + bin], (int)__popc(mm));
            }
        }
        __syncthreads();
        // merge copies 0..15 into copy 0
        #pragma unroll
        for (int j = 0; j < 2; j++) {
            int bin = tid + j * 1024;
            int s = 0;
            #pragma unroll
            for (int c2 = 0; c2 < NCOPY; c2++) s += h[(c2 << 11) + bin];
            h[bin] = s;
        }
        __syncthreads();
        sel = find_threshold(h, 2048, tid, &s_kr, &s_res, s_seg);
        pref |= (unsigned)sel << 10; prefmask = 0xFFFFFC00u;

        // pass 3: bits [9:0] — privatized (bins 0..1023 of each copy)
        #pragma unroll
        for (int j = 0; j < NCOPY * NBIN / 1024; j++) h[tid + j * 1024] = 0;
        __syncthreads();
        #pragma unroll
        for (int i = 0; i < 32; i++) {
            bool hit = (v[i] & prefmask) == pref;
            unsigned act = __ballot_sync(0xffffffffu, hit);
            if (hit) {
                int bin = (int)(v[i] & 0x3FFu);
                unsigned mm = __match_any_sync(act, bin);
                if ((mm & ((1u << lane) - 1u)) == 0u)
                    atomicAdd(&h[hbase + bin], (int)__popc(mm));
            }
        }
        __syncthreads();
        {
            int bin = tid;                       // 1024 bins, one per thread
            int s = 0;
            #pragma unroll
            for (int c2 = 0; c2 < NCOPY; c2++) s += h[(c2 << 11) + bin];
            h[bin] = s;
        }
        __syncthreads();
        sel = find_threshold(h, 1024, tid, &s_kr, &s_res, s_seg);
        pref |= (unsigned)sel;

        const unsigned tbits = pref;
        const int kr = s_kr;
        float acc = 0.0f;
        #pragma unroll
        for (int i = 0; i < 32; i++)
            if (v[i] > tbits) acc += __uint_as_float(v[i]);
        #pragma unroll
        for (int o = 16; o; o >>= 1) acc += __shfl_down_sync(0xffffffffu, acc, o);
        if (lane == 0) sw32[w] = acc;
        __syncthreads();
        if (tid < 32) {
            float x = sw32[tid];
            #pragma unroll
            for (int o = 16; o; o >>= 1) x += __shfl_down_sync(0xffffffffu, x, o);
            if (tid == 0) s_topk = x + (float)kr * __uint_as_float(tbits);
        }
    } else {
        if (tid == 0) s_topk = 0.0f;
    }
    __syncthreads();

    if (tid == 0) {
        g_bt[b] = s_topk;
        __threadfence();
        int prev = atomicAdd(&g_done, 1);
        if (prev == BB - 1) {
            __threadfence();
            float sl = 0.f, sc = 0.f; int sn = 0;
            for (int b2 = 0; b2 < BB; b2++) {
                sl += g_bl[b2];
                sc += g_bc[b2] + g_bt[b2];
                sn += g_bn[b2];
            }
            float N = (float)sn;
            out[0] = sl / N;
            out[1] = sc / N;
            g_done = 0;   // reset for next replay
        }
    }
}

extern "C" void kernel_launch(void* const* d_in, const int* in_sizes, int n_in,
                              void* d_out, int out_size) {
    const float*  loc     = (const float*)d_in[0];   // (B, P, 3)
    const float2* conf    = (const float2*)d_in[1];  // (B, P, 2)
    const float4* priors  = (const float4*)d_in[2];  // (P, 4)
    const float*  targets = (const float*)d_in[3];   // (B, O, 5)
    float* out = (float*)d_out;

    cudaFuncSetAttribute(k_select, cudaFuncAttributeMaxDynamicSharedMemorySize, SEL_SMEM);
    k_main<<<dim3(NBLK, BB), CBLK>>>(loc, conf, priors, targets);
    k_select<<<BB, 1024, SEL_SMEM>>>(out);
}

// round 16
// speedup vs baseline: 1.0676x; 1.0676x over previous
#include <cuda_runtime.h>

#define BB 32
#define PP 32768
#define OO 32
#define CBLK 256
#define NBLK (PP / CBLK)   // 128
#define NBIN 2048

// ---------------- scratch (zero-initialized at module load; self-resetting) ----
__device__ unsigned long long g_bp_key[BB * OO];   // 0 is a valid identity for atomicMax
__device__ float g_ce[BB * PP];
__device__ int   g_hist[BB * NBIN];                // zeroed by k_select after use
__device__ float g_pl[BB * NBLK], g_pc[BB * NBLK];
__device__ int   g_pn[BB * NBLK];
__device__ float g_cl[BB], g_cc[BB];
__device__ int   g_cn[BB];
__device__ float g_bl[BB], g_bc[BB], g_bt[BB];
__device__ int   g_bn[BB];
__device__ int   g_bdone[BB];                      // per-batch block-completion counter
__device__ int   g_done;                           // reset by finalizer

// ---------------- shared math helpers ----------------
__device__ __forceinline__ float iou_f(float tx1, float ty1, float tx2, float ty2, float tar,
                                       float px1, float py1, float px2, float py2, float pa) {
    float ww = fmaxf(fminf(tx2, px2) - fmaxf(tx1, px1), 0.0f);
    float hh = fmaxf(fminf(ty2, py2) - fmaxf(ty1, py1), 0.0f);
    float inter = ww * hh;
    return __fdividef(inter, (tar + pa) - inter);
}

__device__ __forceinline__ void loss_terms(float ov, float lbl,
                                           float mtx1, float mty1, float mtx2, float mty2,
                                           float prx, float pry, float prz, float prw,
                                           float q0, float q1, float q2,
                                           float cx, float cy,
                                           bool& pos, float& lloss, float& ce, float& cem) {
    int cls = (ov < 0.5f) ? 0 : (int)lbl;
    pos = cls > 0;
    float gx = __fdividef((mtx1 + mtx2) * 0.5f - prx, 0.1f * prz);
    float gy = __fdividef((mty1 + mty2) * 0.5f - pry, 0.1f * prw);
    float gw = __logf(__fdividef(mtx2 - mtx1, prz)) * 5.0f;
    float gh = __logf(__fdividef(mty2 - mty1, prw)) * 5.0f;
    float d0 = q0 - gx, d1 = q1 - gy, d2 = q2 - gw, d3 = q2 - gh;
    float a0 = fabsf(d0), a1 = fabsf(d1), a2 = fabsf(d2), a3 = fabsf(d3);
    float t0 = (a0 < 1.0f) ? 0.5f * d0 * d0 : a0 - 0.5f;
    float t1 = (a1 < 1.0f) ? 0.5f * d1 * d1 : a1 - 0.5f;
    float t2 = (a2 < 1.0f) ? 0.5f * d2 * d2 : a2 - 0.5f;
    float t3 = (a3 < 1.0f) ? 0.5f * d3 * d3 : a3 - 0.5f;
    lloss = (t0 + t1) + (t2 + t3);
    float m = fmaxf(cx, cy);
    float lse = m + __logf(__expf(cx - m) + __expf(cy - m));
    float picked = cls ? cy : cx;
    ce = lse - picked;
    cem = pos ? 0.0f : fmaxf(ce, 0.0f);
}

// ---------------- override correction (warp 0 of the last block per batch) ----
// __noinline__ firewall: keeps the tail's register demand out of the hot loop.
__device__ __noinline__ void do_correction(int b, int lane,
                                           const float*  __restrict__ loc,
                                           const float2* __restrict__ conf,
                                           const float4* __restrict__ priors,
                                           const float4* s_tb, const float* s_ta,
                                           const float* s_tl) {
    __threadfence();                         // acquire: other blocks' g_ce/g_bp_key/g_hist
    const int o = lane;
    unsigned p = 0xFFFFFFFFu - (unsigned)(g_bp_key[b * OO + o] & 0xFFFFFFFFull);
    g_bp_key[b * OO + o] = 0ull;             // reset for next replay (0 = valid identity)
    unsigned mm = __match_any_sync(0xffffffffu, p);
    bool active = (31 - __clz(mm)) == o;     // last-o-wins dedup

    float4 pr = priors[p];
    float px1 = pr.x - pr.z * 0.5f, py1 = pr.y - pr.w * 0.5f;
    float px2 = pr.x + pr.z * 0.5f, py2 = pr.y + pr.w * 0.5f;
    float pa = (px2 - px1) * (py2 - py1);

    // recompute old best_truth with the SAME math/order as the main loop
    unsigned obu = 0u; int obi = 0;
    #pragma unroll
    for (int o2 = 0; o2 < OO; o2++) {
        float4 tb = s_tb[o2];
        float iou = iou_f(tb.x, tb.y, tb.z, tb.w, s_ta[o2],
                          px1, py1, px2, py2, pa);
        unsigned u = __float_as_uint(iou);
        if (u > obu) { obu = u; obi = o2; }
    }
    float obv = __uint_as_float(obu);

    const size_t bp = (size_t)b * PP + p;
    const float* l = loc + bp * 3;
    float q0 = l[0], q1 = l[1], q2 = l[2];
    float2 c = conf[bp];

    float4 tbo = s_tb[obi];
    bool pos_o; float ll_o, ce_o, cem_o;
    loss_terms(obv, s_tl[obi], tbo.x, tbo.y, tbo.z, tbo.w,
               pr.x, pr.y, pr.z, pr.w, q0, q1, q2, c.x, c.y,
               pos_o, ll_o, ce_o, cem_o);
    float4 tbn = s_tb[o];
    bool pos_n; float ll_n, ce_n, cem_n;
    loss_terms(2.0f, s_tl[o], tbn.x, tbn.y, tbn.z, tbn.w,
               pr.x, pr.y, pr.z, pr.w, q0, q1, q2, c.x, c.y,
               pos_n, ll_n, ce_n, cem_n);

    float dl = 0.f, dc = 0.f; int dn = 0;
    if (active) {
        float stored = g_ce[bp];             // exact bits the owning block wrote
        g_ce[bp] = cem_n;
        int ob = (int)(__float_as_uint(stored) >> 21);
        int nb = (int)(__float_as_uint(cem_n) >> 21);
        if (ob != nb) {
            atomicAdd(&g_hist[b * NBIN + ob], -1);
            atomicAdd(&g_hist[b * NBIN + nb], 1);
        }
        dl = (pos_n ? ll_n : 0.f) - (pos_o ? ll_o : 0.f);
        dc = (pos_n ? ce_n : 0.f) - (pos_o ? ce_o : 0.f);
        dn = (pos_n ? 1 : 0) - (pos_o ? 1 : 0);
    }
    #pragma unroll
    for (int s = 16; s; s >>= 1) {
        dl += __shfl_down_sync(0xffffffffu, dl, s);
        dc += __shfl_down_sync(0xffffffffu, dc, s);
        dn += __shfl_down_sync(0xffffffffu, dn, s);
    }
    if (o == 0) { g_cl[b] = dl; g_cc[b] = dc; g_cn[b] = dn; g_bdone[b] = 0; }
}

// ---------------- fused match + loss + histogram + tail correction -----------
__global__ __launch_bounds__(CBLK, 6) void k_main(const float*  __restrict__ loc,
                                                  const float2* __restrict__ conf,
                                                  const float4* __restrict__ priors,
                                                  const float*  __restrict__ targets) {
    __shared__ float4 s_tb[OO];                  // truth box (x1,y1,x2,y2)
    __shared__ float  s_ta[OO];                  // truth area
    __shared__ float  s_tl[OO];                  // truth label
    __shared__ unsigned long long sbest[OO];
    __shared__ unsigned s_m[8][OO * 33];         // per-warp 32x32 iou tile, padded
    __shared__ float swl[8], swc[8];
    __shared__ int   swn[8];
    __shared__ int   s_prev;
    const int b = blockIdx.y, tid = threadIdx.x;
    const int lane = tid & 31, w = tid >> 5;

    if (tid < OO) {
        const float* t = targets + (size_t)(b * OO + tid) * 5;
        float x1 = t[0], y1 = t[1], x2 = t[2], y2 = t[3];
        s_tb[tid] = make_float4(x1, y1, x2, y2);
        s_ta[tid] = (x2 - x1) * (y2 - y1);
        s_tl[tid] = t[4];
        sbest[tid] = 0ull;
    }
    const int pblk = blockIdx.x * CBLK;
    const int p = pblk + tid;
    float4 pr = priors[p];
    const float Px1 = pr.x - pr.z * 0.5f, Py1 = pr.y - pr.w * 0.5f;
    const float Px2 = pr.x + pr.z * 0.5f, Py2 = pr.y + pr.w * 0.5f;
    const float Pa  = (Px2 - Px1) * (Py2 - Py1);
    __syncthreads();

    unsigned* mrow = s_m[w];
    unsigned best_u = 0u; int best_o = 0;        // per-prior best truth (local)

    #pragma unroll
    for (int o = 0; o < 32; o++) {
        float4 tb = s_tb[o];                     // LDS.128 broadcast
        float  ta = s_ta[o];                     // LDS.32 broadcast
        float ww = fmaxf(fminf(tb.z, Px2) - fmaxf(tb.x, Px1), 0.0f);
        float hh = fmaxf(fminf(tb.w, Py2) - fmaxf(tb.y, Py1), 0.0f);
        float inter = ww * hh;
        float iou = __fdividef(inter, (ta + Pa) - inter);
        unsigned u = __float_as_uint(iou);
        mrow[lane * 33 + o] = u;                 // conflict-free STS
        if (u > best_u) { best_u = u; best_o = o; }   // first-index on ties
    }
    __syncwarp();

    // per-truth argmax over this warp's 32 priors (lane = truth)
    {
        unsigned tu = 0u; int tk = 0;
        #pragma unroll
        for (int k = 0; k < 32; k++) {
            unsigned u = mrow[k * 33 + lane];
            if (u > tu) { tu = u; tk = k; }      // ascending prior index, strict > = first
        }
        unsigned long long key = ((unsigned long long)tu << 32) |
                                 (unsigned)(0xFFFFFFFFu - (unsigned)(pblk + w * 32 + tk));
        atomicMax(&sbest[lane], key);
    }

    // ---- loss for my prior ----
    const size_t bp = (size_t)b * PP + p;
    const int idx = best_o;
    const float my_bto = __uint_as_float(best_u);
    float4 tb2 = s_tb[idx];
    const float* l = loc + bp * 3;
    float q0 = l[0], q1 = l[1], q2 = l[2];
    float2 c = conf[bp];

    bool pos; float lloss, ce, cem;
    loss_terms(my_bto, s_tl[idx],
               tb2.x, tb2.y, tb2.z, tb2.w,
               pr.x, pr.y, pr.z, pr.w, q0, q1, q2, c.x, c.y,
               pos, lloss, ce, cem);
    g_ce[bp] = cem;

    {   // distributed warp-aggregated histogram of ce_mine top-11 bits
        unsigned bin = __float_as_uint(cem) >> 21;
        unsigned mm = __match_any_sync(0xffffffffu, bin);
        if ((mm & ((1u << lane) - 1u)) == 0u)
            atomicAdd(&g_hist[b * NBIN + bin], (int)__popc(mm));
    }

    float rl = pos ? lloss : 0.0f;
    float rc = pos ? ce : 0.0f;
    int   rn = pos ? 1 : 0;
    #pragma unroll
    for (int o = 16; o; o >>= 1) {
        rl += __shfl_down_sync(0xffffffffu, rl, o);
        rc += __shfl_down_sync(0xffffffffu, rc, o);
        rn += __shfl_down_sync(0xffffffffu, rn, o);
    }
    if (lane == 0) { swl[w] = rl; swc[w] = rc; swn[w] = rn; }
    __syncthreads();
    if (tid == 0) {
        float sl = 0.f, sc = 0.f; int sn = 0;
        #pragma unroll
        for (int i = 0; i < 8; i++) { sl += swl[i]; sc += swc[i]; sn += swn[i]; }
        int pb = b * NBLK + blockIdx.x;
        g_pl[pb] = sl; g_pc[pb] = sc; g_pn[pb] = sn;
    }
    if (tid < OO) atomicMax(&g_bp_key[b * OO + tid], sbest[tid]);

    // ---- tail: last block of this batch runs the override correction ----
    __syncthreads();                             // all block writes issued
    if (tid == 0) {
        __threadfence();                         // release this block's writes
        s_prev = atomicAdd(&g_bdone[b], 1);
    }
    __syncthreads();
    if (s_prev == NBLK - 1 && w == 0)
        do_correction(b, lane, loc, conf, priors, s_tb, s_ta, s_tl);
}

// ---------------- hierarchical threshold finder (2 barriers) ----------------
__device__ __forceinline__ int find_threshold(int* h, int n, int tid,
                                              int* s_kr, int* s_res, int* s_seg) {
    const int lane = tid & 31, w = tid >> 5;
    const int nseg = n >> 6;   // 64 bins per segment, one warp each
    if (w < nseg) {
        int a = h[(w << 6) + lane] + h[(w << 6) + 32 + lane];
        #pragma unroll
        for (int o = 16; o; o >>= 1) a += __shfl_down_sync(0xffffffffu, a, o);
        if (lane == 0) s_seg[w] = a;
    }
    __syncthreads();
    if (w == 0) {
        int kr = *s_kr;
        int vv = (lane < nseg) ? s_seg[lane] : 0;
        #pragma unroll
        for (int o = 1; o < 32; o <<= 1) {
            int u = __shfl_down_sync(0xffffffffu, vv, o);
            if (lane + o < 32) vv += u;
        }
        unsigned bal = __ballot_sync(0xffffffffu, vv >= kr);
        int seg = 31 - __clz(bal);
        int above = __shfl_sync(0xffffffffu, vv, (seg + 1) & 31);
        if (seg == 31) above = 0;
        int kr2 = kr - above;
        int base = seg << 6;
        int sh = h[base + 32 + lane];
        #pragma unroll
        for (int o = 1; o < 32; o <<= 1) {
            int u = __shfl_down_sync(0xffffffffu, sh, o);
            if (lane + o < 32) sh += u;
        }
        int hi_total = __shfl_sync(0xffffffffu, sh, 0);
        int sl = h[base + lane];
        #pragma unroll
        for (int o = 1; o < 32; o <<= 1) {
            int u = __shfl_down_sync(0xffffffffu, sl, o);
            if (lane + o < 32) sl += u;
        }
        sl += hi_total;
        unsigned balh = __ballot_sync(0xffffffffu, sh >= kr2);
        int sel, kr3;
        if (balh) {
            int l2 = 31 - __clz(balh);
            sel = base + 32 + l2;
            int ab = __shfl_sync(0xffffffffu, sh, (l2 + 1) & 31);
            if (l2 == 31) ab = 0;
            kr3 = kr2 - ab;
        } else {
            unsigned ball = __ballot_sync(0xffffffffu, sl >= kr2);
            int l2 = 31 - __clz(ball);
            sel = base + l2;
            int ab = (l2 == 31) ? hi_total : __shfl_sync(0xffffffffu, sl, (l2 + 1) & 31);
            kr3 = kr2 - ab;
        }
        if (lane == 0) { *s_res = sel; *s_kr = kr3; }
    }
    __syncthreads();
    return *s_res;
}

// ---------------- per-batch top-k + finalize (lean loops) ----------------
__global__ __launch_bounds__(1024) void k_select(float* __restrict__ out) {
    __shared__ int h[NBIN];
    __shared__ int s_seg[32];
    __shared__ float sw32[32];
    __shared__ int s_kr, s_k, s_res;
    __shared__ float s_topk;
    const int b = blockIdx.x, tid = threadIdx.x;
    const int lane = tid & 31, w = tid >> 5;

    // load ce values first — warp-contiguous LDG.128 (order-free mapping)
    unsigned v[32];
    {
        const uint4* ce4 = (const uint4*)(g_ce + (size_t)b * PP);
        #pragma unroll
        for (int i = 0; i < 8; i++) {
            uint4 f = ce4[tid + i * 1024];
            v[i * 4 + 0] = f.x;
            v[i * 4 + 1] = f.y;
            v[i * 4 + 2] = f.z;
            v[i * 4 + 3] = f.w;
        }
    }

    // pass-1 histogram comes precomputed; zero it for the next replay
    h[tid]        = g_hist[b * NBIN + tid];
    h[tid + 1024] = g_hist[b * NBIN + tid + 1024];
    g_hist[b * NBIN + tid] = 0;
    g_hist[b * NBIN + tid + 1024] = 0;

    if (w == 0) {
        float a = 0.f, c = 0.f; int nn = 0;
        #pragma unroll
        for (int j = 0; j < 4; j++) {
            int pb = b * NBLK + lane + 32 * j;
            a += g_pl[pb]; c += g_pc[pb]; nn += g_pn[pb];
        }
        #pragma unroll
        for (int o = 16; o; o >>= 1) {
            a  += __shfl_down_sync(0xffffffffu, a, o);
            c  += __shfl_down_sync(0xffffffffu, c, o);
            nn += __shfl_down_sync(0xffffffffu, nn, o);
        }
        if (lane == 0) {
            a += g_cl[b]; c += g_cc[b]; nn += g_cn[b];
            g_bl[b] = a; g_bc[b] = c; g_bn[b] = nn;
            int k = 3 * nn; if (k > PP - 1) k = PP - 1;
            s_k = k; s_kr = k;
        }
    }
    __syncthreads();

    if (s_k > 0) {
        // pass 1: bits [31:21] (precomputed)
        int sel = find_threshold(h, 2048, tid, &s_kr, &s_res, s_seg);
        unsigned pref = (unsigned)sel << 21, prefmask = 0xFFE00000u;

        // pass 2: bits [20:10] — lean: predicated atomicAdd, no collectives
        h[tid] = 0; h[tid + 1024] = 0;
        __syncthreads();
        #pragma unroll
        for (int i = 0; i < 32; i++) {
            if ((v[i] & prefmask) == pref)
                atomicAdd(&h[(v[i] >> 10) & 0x7FFu], 1);
        }
        __syncthreads();
        sel = find_threshold(h, 2048, tid, &s_kr, &s_res, s_seg);
        pref |= (unsigned)sel << 10; prefmask = 0xFFFFFC00u;

        // pass 3: bits [9:0] — lean
        h[tid] = 0; h[tid + 1024] = 0;
        __syncthreads();
        #pragma unroll
        for (int i = 0; i < 32; i++) {
            if ((v[i] & prefmask) == pref)
                atomicAdd(&h[v[i] & 0x3FFu], 1);
        }
        __syncthreads();
        sel = find_threshold(h, 1024, tid, &s_kr, &s_res, s_seg);
        pref |= (unsigned)sel;

        const unsigned tbits = pref;
        const int kr = s_kr;
        float acc = 0.0f;
        #pragma unroll
        for (int i = 0; i < 32; i++)
            if (v[i] > tbits) acc += __uint_as_float(v[i]);
        #pragma unroll
        for (int o = 16; o; o >>= 1) acc += __shfl_down_sync(0xffffffffu, acc, o);
        if (lane == 0) sw32[w] = acc;
        __syncthreads();
        if (tid < 32) {
            float x = sw32[tid];
            #pragma unroll
            for (int o = 16; o; o >>= 1) x += __shfl_down_sync(0xffffffffu, x, o);
            if (tid == 0) s_topk = x + (float)kr * __uint_as_float(tbits);
        }
    } else {
        if (tid == 0) s_topk = 0.0f;
    }
    __syncthreads();

    if (tid == 0) {
        g_bt[b] = s_topk;
        __threadfence();
        int prev = atomicAdd(&g_done, 1);
        if (prev == BB - 1) {
            __threadfence();
            float sl = 0.f, sc = 0.f; int sn = 0;
            for (int b2 = 0; b2 < BB; b2++) {
                sl += g_bl[b2];
                sc += g_bc[b2] + g_bt[b2];
                sn += g_bn[b2];
            }
            float N = (float)sn;
            out[0] = sl / N;
            out[1] = sc / N;
            g_done = 0;   // reset for next replay
        }
    }
}

extern "C" void kernel_launch(void* const* d_in, const int* in_sizes, int n_in,
                              void* d_out, int out_size) {
    const float*  loc     = (const float*)d_in[0];   // (B, P, 3)
    const float2* conf    = (const float2*)d_in[1];  // (B, P, 2)
    const float4* priors  = (const float4*)d_in[2];  // (P, 4)
    const float*  targets = (const float*)d_in[3];   // (B, O, 5)
    float* out = (float*)d_out;

    k_main<<<dim3(NBLK, BB), CBLK>>>(loc, conf, priors, targets);
    k_select<<<BB, 1024>>>(out);
}